// round 2
// baseline (speedup 1.0000x reference)
#include <cuda_runtime.h>
#include <math.h>

// ---------------------------------------------------------------------------
// Problem constants
// ---------------------------------------------------------------------------
#define Bn  2
#define Sn  1024
#define Dn  1024
#define Mn  8
#define Rn  128
#define NNEUR 256
#define NH  16
#define DH  64
#define BS  (Bn * Sn)          // 2048 tokens

// ---------------------------------------------------------------------------
// Device scratch (allocation-free: __device__ globals)
// ---------------------------------------------------------------------------
__device__ float d_logits[3 * BS * NNEUR];     // router logits (q,k,v)
__device__ float d_g[3 * BS * Mn];             // grouped gates (q,k,v)
__device__ float d_allh_qk[BS * Mn * Rn];      // x @ qk_f[m]
__device__ float d_allh_v [BS * Mn * Rn];      // x @ v_f[m]
__device__ float d_hq[BS * Rn];
__device__ float d_hk[BS * Rn];
__device__ float d_hv[BS * Rn];
__device__ float d_aeff[BS * (Mn * Rn)];       // (g ⊗ h), reused for Q,K,V
__device__ float d_Qb[BS * Dn];
__device__ float d_Kb[BS * Dn];
__device__ float d_Vb[BS * Dn];
__device__ float d_attn[BS * Dn];

// ---------------------------------------------------------------------------
// Generic fp32 tiled GEMM: C = A @ B  (row-major), optional z-batching.
// BM=BN=128, BK=8, 256 threads, 8x8 micro-tile. All dims must divide tiles
// exactly (they do for every call in this pipeline).
// ---------------------------------------------------------------------------
__global__ void __launch_bounds__(256)
sgemm_kernel(const float* __restrict__ A, const float* __restrict__ B,
             float* __restrict__ C,
             int Mdim, int Ndim, int Kdim,
             int lda, int ldb, int ldc,
             long long sA, long long sB, long long sC)
{
    A += (long long)blockIdx.z * sA;
    B += (long long)blockIdx.z * sB;
    C += (long long)blockIdx.z * sC;

    __shared__ float As[8][128];
    __shared__ float Bs[8][128];

    const int tid  = threadIdx.x;
    const int brow = blockIdx.y * 128;
    const int bcol = blockIdx.x * 128;

    // A tile load mapping: 128x8 = 1024 elems, float4 per thread
    const int aIdx = tid * 4;
    const int aRow = aIdx >> 3;          // /8
    const int aCol = aIdx & 7;           // 0 or 4
    // B tile load mapping: 8x128
    const int bIdx = tid * 4;
    const int bRow = bIdx >> 7;          // /128
    const int bCol = bIdx & 127;

    const int tx = tid & 15;
    const int ty = tid >> 4;

    const float* Aptr = A + (size_t)(brow + aRow) * lda + aCol;
    const float* Bptr = B + (size_t)bRow * ldb + bcol + bCol;

    float acc[8][8];
#pragma unroll
    for (int i = 0; i < 8; i++)
#pragma unroll
        for (int j = 0; j < 8; j++) acc[i][j] = 0.f;

    for (int k0 = 0; k0 < Kdim; k0 += 8) {
        float4 av = *(const float4*)Aptr;
        float4 bv = *(const float4*)Bptr;
        Aptr += 8;
        Bptr += (size_t)8 * ldb;

        As[aCol + 0][aRow] = av.x;
        As[aCol + 1][aRow] = av.y;
        As[aCol + 2][aRow] = av.z;
        As[aCol + 3][aRow] = av.w;
        *(float4*)&Bs[bRow][bCol] = bv;
        __syncthreads();

#pragma unroll
        for (int k = 0; k < 8; k++) {
            float4 a0 = *(const float4*)&As[k][ty * 8];
            float4 a1 = *(const float4*)&As[k][ty * 8 + 4];
            float4 b0 = *(const float4*)&Bs[k][tx * 8];
            float4 b1 = *(const float4*)&Bs[k][tx * 8 + 4];
            float a[8] = {a0.x, a0.y, a0.z, a0.w, a1.x, a1.y, a1.z, a1.w};
            float b[8] = {b0.x, b0.y, b0.z, b0.w, b1.x, b1.y, b1.z, b1.w};
#pragma unroll
            for (int i = 0; i < 8; i++)
#pragma unroll
                for (int j = 0; j < 8; j++)
                    acc[i][j] = fmaf(a[i], b[j], acc[i][j]);
        }
        __syncthreads();
    }

#pragma unroll
    for (int i = 0; i < 8; i++) {
        float* cp = C + (size_t)(brow + ty * 8 + i) * ldc + bcol + tx * 8;
        *(float4*)cp       = make_float4(acc[i][0], acc[i][1], acc[i][2], acc[i][3]);
        *(float4*)(cp + 4) = make_float4(acc[i][4], acc[i][5], acc[i][6], acc[i][7]);
    }
}

// ---------------------------------------------------------------------------
// Gate softmax + grouping: softmax over 256 neurons, sum groups of 32,
// normalize by (total + 1e-8*total) == /(1+1e-8). grid=(BS,3), block=256.
// ---------------------------------------------------------------------------
__global__ void gate_kernel()
{
    const int token = blockIdx.x;
    const int which = blockIdx.y;
    const float* lp = d_logits + ((size_t)which * BS + token) * NNEUR;
    const int t = threadIdx.x;

    __shared__ float red[256];
    __shared__ float gs[8];

    float v = lp[t];
    red[t] = v; __syncthreads();
#pragma unroll
    for (int s = 128; s > 0; s >>= 1) {
        if (t < s) red[t] = fmaxf(red[t], red[t + s]);
        __syncthreads();
    }
    float mx = red[0];
    __syncthreads();

    float e = __expf(v - mx);
    // group = warp (32 consecutive neurons)
#pragma unroll
    for (int off = 16; off; off >>= 1)
        e += __shfl_down_sync(0xffffffffu, e, off);
    if ((t & 31) == 0) gs[t >> 5] = e;
    __syncthreads();

    if (t < 8) {
        float tot = 0.f;
#pragma unroll
        for (int i = 0; i < 8; i++) tot += gs[i];
        d_g[((size_t)which * BS + token) * Mn + t] = gs[t] / (tot * (1.0f + 1e-8f));
    }
}

// ---------------------------------------------------------------------------
// Mix: h[bs,r] = sum_m g[bs,m] * all_h[bs,m,r]  for (hq,hk from qk; hv from v)
// grid = BS, block = 128
// ---------------------------------------------------------------------------
__global__ void mix_kernel()
{
    const int bs = blockIdx.x;
    const int r  = threadIdx.x;
    const float* gq = d_g + (size_t)bs * Mn;
    const float* gk = d_g + (size_t)BS * Mn + (size_t)bs * Mn;
    const float* gv = d_g + (size_t)2 * BS * Mn + (size_t)bs * Mn;

    float hq = 0.f, hk = 0.f, hv = 0.f;
#pragma unroll
    for (int m = 0; m < Mn; m++) {
        float a  = d_allh_qk[(size_t)bs * (Mn * Rn) + m * Rn + r];
        float av = d_allh_v [(size_t)bs * (Mn * Rn) + m * Rn + r];
        hq = fmaf(gq[m], a, hq);
        hk = fmaf(gk[m], a, hk);
        hv = fmaf(gv[m], av, hv);
    }
    d_hq[bs * Rn + r] = hq;
    d_hk[bs * Rn + r] = hk;
    d_hv[bs * Rn + r] = hv;
}

// ---------------------------------------------------------------------------
// Aeff[bs, m*R + r] = g[bs,m] * h[bs,r]     grid = BS, block = 256 (x4 elems)
// ---------------------------------------------------------------------------
__global__ void aeff_kernel(const float* __restrict__ h, const float* __restrict__ g)
{
    const int bs = blockIdx.x;
    const int c  = threadIdx.x * 4;                 // 0..1020
    float gm = g[(size_t)bs * Mn + (c >> 7)];       // c/128 -> m
    float4 hv = *(const float4*)(h + (size_t)bs * Rn + (c & 127));
    float4 o = make_float4(gm * hv.x, gm * hv.y, gm * hv.z, gm * hv.w);
    *(float4*)(d_aeff + (size_t)bs * (Mn * Rn) + c) = o;
}

// ---------------------------------------------------------------------------
// Causal flash attention, 16 heads x d_head=64, fp32.
// One thread per query row (128 rows/block). K/V tiles of 64 rows in smem,
// online softmax processed in chunks of 16 keys.
// grid = (S/128, B*NH), block = 128
// ---------------------------------------------------------------------------
__global__ void __launch_bounds__(128)
flash_kernel()
{
    __shared__ float Ks[64][64];
    __shared__ float Vs[64][64];

    const int tid = threadIdx.x;
    const int bh  = blockIdx.y;
    const int b   = bh >> 4;
    const int h   = bh & 15;
    const int qrow = blockIdx.x * 128 + tid;            // within sequence

    const float* qp = d_Qb + ((size_t)(b * Sn + qrow)) * Dn + h * DH;
    float q[DH];
#pragma unroll
    for (int d4 = 0; d4 < 16; d4++) {
        float4 v = *(const float4*)(qp + d4 * 4);
        q[d4 * 4 + 0] = v.x; q[d4 * 4 + 1] = v.y;
        q[d4 * 4 + 2] = v.z; q[d4 * 4 + 3] = v.w;
    }

    float o[DH];
#pragma unroll
    for (int d = 0; d < DH; d++) o[d] = 0.f;
    float mrun = -1e30f, lrun = 0.f;

    const int rowMax = blockIdx.x * 128 + 127;
    const float scale = 0.125f;                          // 1/sqrt(64)

    for (int kc = 0; kc <= rowMax; kc += 64) {
        // cooperative tile load: 64 rows x 16 float4 each
#pragma unroll
        for (int i = 0; i < 8; i++) {
            int f   = tid + i * 128;                     // 0..1023
            int row = f >> 4;
            int c4  = (f & 15) * 4;
            size_t gidx = ((size_t)(b * Sn + kc + row)) * Dn + h * DH + c4;
            *(float4*)&Ks[row][c4] = *(const float4*)(d_Kb + gidx);
            *(float4*)&Vs[row][c4] = *(const float4*)(d_Vb + gidx);
        }
        __syncthreads();

#pragma unroll 1
        for (int c = 0; c < 4; c++) {
            int jbase = kc + c * 16;
            if (jbase <= qrow) {
                float s[16];
                float mloc = mrun;
#pragma unroll
                for (int jj = 0; jj < 16; jj++) {
                    int j = c * 16 + jj;
                    const float4* kp = (const float4*)&Ks[j][0];
                    float accv = 0.f;
#pragma unroll
                    for (int d4 = 0; d4 < 16; d4++) {
                        float4 kv = kp[d4];
                        accv = fmaf(q[d4 * 4 + 0], kv.x, accv);
                        accv = fmaf(q[d4 * 4 + 1], kv.y, accv);
                        accv = fmaf(q[d4 * 4 + 2], kv.z, accv);
                        accv = fmaf(q[d4 * 4 + 3], kv.w, accv);
                    }
                    accv *= scale;
                    if (jbase + jj > qrow) accv = -3.0e38f;
                    s[jj] = accv;
                    mloc = fmaxf(mloc, accv);
                }
                float corr = __expf(mrun - mloc);
                mrun = mloc;
                lrun *= corr;
#pragma unroll
                for (int d = 0; d < DH; d++) o[d] *= corr;
#pragma unroll
                for (int jj = 0; jj < 16; jj++) {
                    float p = __expf(s[jj] - mrun);
                    lrun += p;
                    const float4* vp = (const float4*)&Vs[c * 16 + jj][0];
#pragma unroll
                    for (int d4 = 0; d4 < 16; d4++) {
                        float4 vv = vp[d4];
                        o[d4 * 4 + 0] = fmaf(p, vv.x, o[d4 * 4 + 0]);
                        o[d4 * 4 + 1] = fmaf(p, vv.y, o[d4 * 4 + 1]);
                        o[d4 * 4 + 2] = fmaf(p, vv.z, o[d4 * 4 + 2]);
                        o[d4 * 4 + 3] = fmaf(p, vv.w, o[d4 * 4 + 3]);
                    }
                }
            }
            // no sync needed inside chunks (per-thread state only)
        }
        __syncthreads();
    }

    float inv = 1.f / lrun;
    float* op = d_attn + ((size_t)(b * Sn + qrow)) * Dn + h * DH;
#pragma unroll
    for (int d4 = 0; d4 < 16; d4++) {
        float4 v = make_float4(o[d4 * 4 + 0] * inv, o[d4 * 4 + 1] * inv,
                               o[d4 * 4 + 2] * inv, o[d4 * 4 + 3] * inv);
        *(float4*)(op + d4 * 4) = v;
    }
}

// ---------------------------------------------------------------------------
// Host launch
// ---------------------------------------------------------------------------
extern "C" void kernel_launch(void* const* d_in, const int* in_sizes, int n_in,
                              void* d_out, int out_size)
{
    const float* x    = (const float*)d_in[0];
    const float* qk_f = (const float*)d_in[1];
    const float* qk_r = (const float*)d_in[2];
    const float* v_f  = (const float*)d_in[3];
    const float* v_r  = (const float*)d_in[4];
    const float* Wgq  = (const float*)d_in[5];
    const float* Wgk  = (const float*)d_in[6];
    const float* Wgv  = (const float*)d_in[7];
    const float* W_O  = (const float*)d_in[8];
    float* out = (float*)d_out;

    float *logits, *g, *allhqk, *allhv, *hq, *hk, *hv, *aeff, *Qb, *Kb, *Vb, *attn;
    cudaGetSymbolAddress((void**)&logits, d_logits);
    cudaGetSymbolAddress((void**)&g,      d_g);
    cudaGetSymbolAddress((void**)&allhqk, d_allh_qk);
    cudaGetSymbolAddress((void**)&allhv,  d_allh_v);
    cudaGetSymbolAddress((void**)&hq,     d_hq);
    cudaGetSymbolAddress((void**)&hk,     d_hk);
    cudaGetSymbolAddress((void**)&hv,     d_hv);
    cudaGetSymbolAddress((void**)&aeff,   d_aeff);
    cudaGetSymbolAddress((void**)&Qb,     d_Qb);
    cudaGetSymbolAddress((void**)&Kb,     d_Kb);
    cudaGetSymbolAddress((void**)&Vb,     d_Vb);
    cudaGetSymbolAddress((void**)&attn,   d_attn);

    dim3 t256(256);

    // 1) Router logits: [2048,256] = x @ Wg_*
    sgemm_kernel<<<dim3(NNEUR / 128, BS / 128, 1), t256>>>(
        x, Wgq, logits,               BS, NNEUR, Dn, Dn, NNEUR, NNEUR, 0, 0, 0);
    sgemm_kernel<<<dim3(NNEUR / 128, BS / 128, 1), t256>>>(
        x, Wgk, logits + (size_t)BS * NNEUR,     BS, NNEUR, Dn, Dn, NNEUR, NNEUR, 0, 0, 0);
    sgemm_kernel<<<dim3(NNEUR / 128, BS / 128, 1), t256>>>(
        x, Wgv, logits + (size_t)2 * BS * NNEUR, BS, NNEUR, Dn, Dn, NNEUR, NNEUR, 0, 0, 0);

    // 2) Softmax + group -> gates
    gate_kernel<<<dim3(BS, 3), 256>>>();

    // 3) all_h[bs,m,r] = x @ qk_f[m] / v_f[m]  (batched over m in grid.z)
    sgemm_kernel<<<dim3(1, BS / 128, Mn), t256>>>(
        x, qk_f, allhqk, BS, Rn, Dn, Dn, Rn, Mn * Rn,
        0, (long long)Dn * Rn, Rn);
    sgemm_kernel<<<dim3(1, BS / 128, Mn), t256>>>(
        x, v_f, allhv,  BS, Rn, Dn, Dn, Rn, Mn * Rn,
        0, (long long)Dn * Rn, Rn);

    // 4) Weighted mix -> hQ, hK, hV
    mix_kernel<<<BS, 128>>>();

    // 5) Restore: Q = (gQ ⊗ hQ) @ flat(qk_r)  (same for K; V with v_r)
    aeff_kernel<<<BS, 256>>>(hq, g);
    sgemm_kernel<<<dim3(Dn / 128, BS / 128, 1), t256>>>(
        aeff, qk_r, Qb, BS, Dn, Mn * Rn, Mn * Rn, Dn, Dn, 0, 0, 0);

    aeff_kernel<<<BS, 256>>>(hk, g + (size_t)BS * Mn);
    sgemm_kernel<<<dim3(Dn / 128, BS / 128, 1), t256>>>(
        aeff, qk_r, Kb, BS, Dn, Mn * Rn, Mn * Rn, Dn, Dn, 0, 0, 0);

    aeff_kernel<<<BS, 256>>>(hv, g + (size_t)2 * BS * Mn);
    sgemm_kernel<<<dim3(Dn / 128, BS / 128, 1), t256>>>(
        aeff, v_r, Vb, BS, Dn, Mn * Rn, Mn * Rn, Dn, Dn, 0, 0, 0);

    // 6) Causal multi-head attention
    flash_kernel<<<dim3(Sn / 128, Bn * NH), 128>>>();

    // 7) Output projection -> d_out
    sgemm_kernel<<<dim3(Dn / 128, BS / 128, 1), t256>>>(
        attn, W_O, out, BS, Dn, Dn, Dn, Dn, Dn, 0, 0, 0);
}

// round 3
// speedup vs baseline: 2.6606x; 2.6606x over previous
#include <cuda_runtime.h>
#include <math.h>
#include <stdint.h>

// ---------------------------------------------------------------------------
// Problem constants
// ---------------------------------------------------------------------------
#define Bn  2
#define Sn  1024
#define Dn  1024
#define Mn  8
#define Rn  128
#define NNEUR 256
#define NH  16
#define DH  64
#define BS  (Bn * Sn)          // 2048 tokens
#define NG  768                // packed gate width (3*256)

// ---------------------------------------------------------------------------
// Device scratch (allocation-free: __device__ globals)
// ---------------------------------------------------------------------------
__device__ float d_Wg[Dn * NG];                // packed [Wg_q | Wg_k | Wg_v]
__device__ float d_logits[BS * NG];            // router logits, [token][768]
__device__ float d_g[3 * BS * Mn];             // grouped gates (q,k,v)
__device__ float d_allh_qk[BS * Mn * Rn];      // x @ qk_f[m]
__device__ float d_allh_v [BS * Mn * Rn];      // x @ v_f[m]
__device__ float d_hq[BS * Rn];
__device__ float d_hk[BS * Rn];
__device__ float d_hv[BS * Rn];
__device__ float d_aeffqk[2 * BS * (Mn * Rn)]; // (gQ⊗hQ) ; (gK⊗hK)
__device__ float d_aeffv [BS * (Mn * Rn)];
__device__ float d_QK[2 * BS * Dn];            // Q ; K
__device__ float d_Vb[BS * Dn];
__device__ float d_attn[BS * Dn];

// ---------------------------------------------------------------------------
// TF32 helpers
// ---------------------------------------------------------------------------
__device__ __forceinline__ float to_tf32(float x) {
    uint32_t u;
    asm("cvt.rna.tf32.f32 %0, %1;" : "=r"(u) : "f"(x));
    return __uint_as_float(u);
}

// ---------------------------------------------------------------------------
// TF32 tensor-core GEMM: C = A @ B (row-major), z-batched via strides.
// BM=BN=128, BK=16, 256 threads (8 warps, warp tile 64x32),
// mma.sync m16n8k8 tf32, double-buffered smem, conflict-free fragment LDS
// (row stride 136 ≡ 8 mod 32). All dims must divide tiles exactly.
// ---------------------------------------------------------------------------
__global__ void __launch_bounds__(256, 2)
tf32_gemm(const float* __restrict__ A, const float* __restrict__ B,
          float* __restrict__ C,
          int Kdim, int lda, int ldb, int ldc,
          long long sA, long long sB, long long sC)
{
    A += (long long)blockIdx.z * sA;
    B += (long long)blockIdx.z * sB;
    C += (long long)blockIdx.z * sC;

    __shared__ float As[2][16][136];   // [k][m], padded
    __shared__ float Bs[2][16][136];   // [k][n], padded

    const int tid  = threadIdx.x;
    const int brow = blockIdx.y * 128;
    const int bcol = blockIdx.x * 128;

    const int warp = tid >> 5;
    const int lane = tid & 31;
    const int wm   = warp >> 2;        // 0..1
    const int wn   = warp & 3;         // 0..3
    const int grp  = lane >> 2;        // 0..7
    const int tg   = lane & 3;         // 0..3

    // global->smem mappings (two passes of 256 threads each)
    const int aRow0 = tid >> 2;              // 0..63
    const int aC4   = (tid & 3) << 2;        // 0,4,8,12
    const int bK0   = tid >> 5;              // 0..7
    const int bN4   = (tid & 31) << 2;       // 0..124

    const float* Ap0 = A + (size_t)(brow + aRow0) * lda + aC4;
    const float* Ap1 = A + (size_t)(brow + aRow0 + 64) * lda + aC4;
    const float* Bp0 = B + (size_t)bK0 * ldb + bcol + bN4;
    const float* Bp1 = B + (size_t)(bK0 + 8) * ldb + bcol + bN4;

    float c[4][4][4];
#pragma unroll
    for (int i = 0; i < 4; i++)
#pragma unroll
        for (int j = 0; j < 4; j++)
#pragma unroll
            for (int r = 0; r < 4; r++) c[i][j][r] = 0.f;

    const int kTiles = Kdim >> 4;

    // prologue: tile 0 -> buffer 0
    {
        float4 a0 = *(const float4*)Ap0;
        float4 a1 = *(const float4*)Ap1;
        float4 b0 = *(const float4*)Bp0;
        float4 b1 = *(const float4*)Bp1;
        As[0][aC4 + 0][aRow0] = to_tf32(a0.x);
        As[0][aC4 + 1][aRow0] = to_tf32(a0.y);
        As[0][aC4 + 2][aRow0] = to_tf32(a0.z);
        As[0][aC4 + 3][aRow0] = to_tf32(a0.w);
        As[0][aC4 + 0][aRow0 + 64] = to_tf32(a1.x);
        As[0][aC4 + 1][aRow0 + 64] = to_tf32(a1.y);
        As[0][aC4 + 2][aRow0 + 64] = to_tf32(a1.z);
        As[0][aC4 + 3][aRow0 + 64] = to_tf32(a1.w);
        float4 tb0 = make_float4(to_tf32(b0.x), to_tf32(b0.y), to_tf32(b0.z), to_tf32(b0.w));
        float4 tb1 = make_float4(to_tf32(b1.x), to_tf32(b1.y), to_tf32(b1.z), to_tf32(b1.w));
        *(float4*)&Bs[0][bK0][bN4]     = tb0;
        *(float4*)&Bs[0][bK0 + 8][bN4] = tb1;
    }
    __syncthreads();

    for (int t = 0; t < kTiles; t++) {
        const int buf = t & 1;

        // prefetch next tile into registers
        float4 pa0, pa1, pb0, pb1;
        if (t + 1 < kTiles) {
            const int ko = (t + 1) << 4;
            pa0 = *(const float4*)(Ap0 + ko);
            pa1 = *(const float4*)(Ap1 + ko);
            pb0 = *(const float4*)(Bp0 + (size_t)ko * ldb);
            pb1 = *(const float4*)(Bp1 + (size_t)ko * ldb);
        }

        // compute on current buffer
#pragma unroll
        for (int ks = 0; ks < 2; ks++) {
            const int kb = ks << 3;
            uint32_t af[4][4], bf[4][2];
#pragma unroll
            for (int i = 0; i < 4; i++) {
                const int m0 = wm * 64 + i * 16 + grp;
                af[i][0] = __float_as_uint(As[buf][kb + tg][m0]);
                af[i][1] = __float_as_uint(As[buf][kb + tg][m0 + 8]);
                af[i][2] = __float_as_uint(As[buf][kb + tg + 4][m0]);
                af[i][3] = __float_as_uint(As[buf][kb + tg + 4][m0 + 8]);
            }
#pragma unroll
            for (int j = 0; j < 4; j++) {
                const int n0 = wn * 32 + j * 8 + grp;
                bf[j][0] = __float_as_uint(Bs[buf][kb + tg][n0]);
                bf[j][1] = __float_as_uint(Bs[buf][kb + tg + 4][n0]);
            }
#pragma unroll
            for (int i = 0; i < 4; i++)
#pragma unroll
                for (int j = 0; j < 4; j++) {
                    asm volatile(
                        "mma.sync.aligned.m16n8k8.row.col.f32.tf32.tf32.f32 "
                        "{%0,%1,%2,%3}, {%4,%5,%6,%7}, {%8,%9}, {%0,%1,%2,%3};\n"
                        : "+f"(c[i][j][0]), "+f"(c[i][j][1]),
                          "+f"(c[i][j][2]), "+f"(c[i][j][3])
                        : "r"(af[i][0]), "r"(af[i][1]), "r"(af[i][2]), "r"(af[i][3]),
                          "r"(bf[j][0]), "r"(bf[j][1]));
                }
        }

        // store prefetched tile into other buffer
        if (t + 1 < kTiles) {
            const int nb = buf ^ 1;
            As[nb][aC4 + 0][aRow0] = to_tf32(pa0.x);
            As[nb][aC4 + 1][aRow0] = to_tf32(pa0.y);
            As[nb][aC4 + 2][aRow0] = to_tf32(pa0.z);
            As[nb][aC4 + 3][aRow0] = to_tf32(pa0.w);
            As[nb][aC4 + 0][aRow0 + 64] = to_tf32(pa1.x);
            As[nb][aC4 + 1][aRow0 + 64] = to_tf32(pa1.y);
            As[nb][aC4 + 2][aRow0 + 64] = to_tf32(pa1.z);
            As[nb][aC4 + 3][aRow0 + 64] = to_tf32(pa1.w);
            float4 tb0 = make_float4(to_tf32(pb0.x), to_tf32(pb0.y), to_tf32(pb0.z), to_tf32(pb0.w));
            float4 tb1 = make_float4(to_tf32(pb1.x), to_tf32(pb1.y), to_tf32(pb1.z), to_tf32(pb1.w));
            *(float4*)&Bs[nb][bK0][bN4]     = tb0;
            *(float4*)&Bs[nb][bK0 + 8][bN4] = tb1;
        }
        __syncthreads();
    }

    // epilogue
#pragma unroll
    for (int i = 0; i < 4; i++) {
        const int r0 = brow + wm * 64 + i * 16 + grp;
#pragma unroll
        for (int j = 0; j < 4; j++) {
            const int cc = bcol + wn * 32 + j * 8 + tg * 2;
            *(float2*)&C[(size_t)r0 * ldc + cc]       = make_float2(c[i][j][0], c[i][j][1]);
            *(float2*)&C[(size_t)(r0 + 8) * ldc + cc] = make_float2(c[i][j][2], c[i][j][3]);
        }
    }
}

// ---------------------------------------------------------------------------
// Pack Wg_q/k/v -> d_Wg [D][768]
// ---------------------------------------------------------------------------
__global__ void pack_wg(const float* __restrict__ q, const float* __restrict__ k,
                        const float* __restrict__ v)
{
    const int idx = blockIdx.x * 256 + threadIdx.x;   // over D*NNEUR
    const int d = idx >> 8;
    const int n = idx & 255;
    d_Wg[(size_t)d * NG + n]       = q[idx];
    d_Wg[(size_t)d * NG + 256 + n] = k[idx];
    d_Wg[(size_t)d * NG + 512 + n] = v[idx];
}

// ---------------------------------------------------------------------------
// Gate softmax + grouping. logits layout: [token][768] (q|k|v blocks).
// grid=(BS,3), block=256.
// ---------------------------------------------------------------------------
__global__ void gate_kernel()
{
    const int token = blockIdx.x;
    const int which = blockIdx.y;
    const float* lp = d_logits + (size_t)token * NG + which * NNEUR;
    const int t = threadIdx.x;

    __shared__ float red[256];
    __shared__ float gs[8];

    float v = lp[t];
    red[t] = v; __syncthreads();
#pragma unroll
    for (int s = 128; s > 0; s >>= 1) {
        if (t < s) red[t] = fmaxf(red[t], red[t + s]);
        __syncthreads();
    }
    float mx = red[0];
    __syncthreads();

    float e = __expf(v - mx);
#pragma unroll
    for (int off = 16; off; off >>= 1)
        e += __shfl_down_sync(0xffffffffu, e, off);
    if ((t & 31) == 0) gs[t >> 5] = e;
    __syncthreads();

    if (t < 8) {
        float tot = 0.f;
#pragma unroll
        for (int i = 0; i < 8; i++) tot += gs[i];
        d_g[((size_t)which * BS + token) * Mn + t] = gs[t] / (tot * (1.0f + 1e-8f));
    }
}

// ---------------------------------------------------------------------------
// Mix: h[bs,r] = sum_m g[bs,m] * all_h[bs,m,r]
// ---------------------------------------------------------------------------
__global__ void mix_kernel()
{
    const int bs = blockIdx.x;
    const int r  = threadIdx.x;
    const float* gq = d_g + (size_t)bs * Mn;
    const float* gk = d_g + (size_t)BS * Mn + (size_t)bs * Mn;
    const float* gv = d_g + (size_t)2 * BS * Mn + (size_t)bs * Mn;

    float hq = 0.f, hk = 0.f, hv = 0.f;
#pragma unroll
    for (int m = 0; m < Mn; m++) {
        float a  = d_allh_qk[(size_t)bs * (Mn * Rn) + m * Rn + r];
        float av = d_allh_v [(size_t)bs * (Mn * Rn) + m * Rn + r];
        hq = fmaf(gq[m], a, hq);
        hk = fmaf(gk[m], a, hk);
        hv = fmaf(gv[m], av, hv);
    }
    d_hq[bs * Rn + r] = hq;
    d_hk[bs * Rn + r] = hk;
    d_hv[bs * Rn + r] = hv;
}

// ---------------------------------------------------------------------------
// Aeff for Q,K,V in one pass: Aeff[bs, m*R+r] = g[bs,m]*h[bs,r]
// grid = BS, block = 256 (float4 per thread per target)
// ---------------------------------------------------------------------------
__global__ void aeff3_kernel()
{
    const int bs = blockIdx.x;
    const int cidx = threadIdx.x * 4;               // 0..1020
    const int m = cidx >> 7;
    const int r = cidx & 127;

    const float gq = d_g[(size_t)bs * Mn + m];
    const float gk = d_g[(size_t)BS * Mn + (size_t)bs * Mn + m];
    const float gv = d_g[(size_t)2 * BS * Mn + (size_t)bs * Mn + m];

    float4 hq4 = *(const float4*)(d_hq + (size_t)bs * Rn + r);
    float4 hk4 = *(const float4*)(d_hk + (size_t)bs * Rn + r);
    float4 hv4 = *(const float4*)(d_hv + (size_t)bs * Rn + r);

    *(float4*)(d_aeffqk + (size_t)bs * (Mn * Rn) + cidx) =
        make_float4(gq * hq4.x, gq * hq4.y, gq * hq4.z, gq * hq4.w);
    *(float4*)(d_aeffqk + (size_t)BS * (Mn * Rn) + (size_t)bs * (Mn * Rn) + cidx) =
        make_float4(gk * hk4.x, gk * hk4.y, gk * hk4.z, gk * hk4.w);
    *(float4*)(d_aeffv + (size_t)bs * (Mn * Rn) + cidx) =
        make_float4(gv * hv4.x, gv * hv4.y, gv * hv4.z, gv * hv4.w);
}

// ---------------------------------------------------------------------------
// Causal flash attention, 16 heads x d_head=64, fp32 (unchanged from R2).
// Q at d_QK, K at d_QK + BS*Dn.
// ---------------------------------------------------------------------------
__global__ void __launch_bounds__(128)
flash_kernel()
{
    __shared__ float Ks[64][64];
    __shared__ float Vs[64][64];

    const int tid = threadIdx.x;
    const int bh  = blockIdx.y;
    const int b   = bh >> 4;
    const int h   = bh & 15;
    const int qrow = blockIdx.x * 128 + tid;

    const size_t Koff = (size_t)BS * Dn;

    const float* qp = d_QK + ((size_t)(b * Sn + qrow)) * Dn + h * DH;
    float q[DH];
#pragma unroll
    for (int d4 = 0; d4 < 16; d4++) {
        float4 v = *(const float4*)(qp + d4 * 4);
        q[d4 * 4 + 0] = v.x; q[d4 * 4 + 1] = v.y;
        q[d4 * 4 + 2] = v.z; q[d4 * 4 + 3] = v.w;
    }

    float o[DH];
#pragma unroll
    for (int d = 0; d < DH; d++) o[d] = 0.f;
    float mrun = -1e30f, lrun = 0.f;

    const int rowMax = blockIdx.x * 128 + 127;
    const float scale = 0.125f;

    for (int kc = 0; kc <= rowMax; kc += 64) {
#pragma unroll
        for (int i = 0; i < 8; i++) {
            int f   = tid + i * 128;
            int row = f >> 4;
            int c4  = (f & 15) * 4;
            size_t gidx = ((size_t)(b * Sn + kc + row)) * Dn + h * DH + c4;
            *(float4*)&Ks[row][c4] = *(const float4*)(d_QK + Koff + gidx);
            *(float4*)&Vs[row][c4] = *(const float4*)(d_Vb + gidx);
        }
        __syncthreads();

#pragma unroll 1
        for (int cch = 0; cch < 4; cch++) {
            int jbase = kc + cch * 16;
            if (jbase <= qrow) {
                float s[16];
                float mloc = mrun;
#pragma unroll
                for (int jj = 0; jj < 16; jj++) {
                    int j = cch * 16 + jj;
                    const float4* kp = (const float4*)&Ks[j][0];
                    float accv = 0.f;
#pragma unroll
                    for (int d4 = 0; d4 < 16; d4++) {
                        float4 kv = kp[d4];
                        accv = fmaf(q[d4 * 4 + 0], kv.x, accv);
                        accv = fmaf(q[d4 * 4 + 1], kv.y, accv);
                        accv = fmaf(q[d4 * 4 + 2], kv.z, accv);
                        accv = fmaf(q[d4 * 4 + 3], kv.w, accv);
                    }
                    accv *= scale;
                    if (jbase + jj > qrow) accv = -3.0e38f;
                    s[jj] = accv;
                    mloc = fmaxf(mloc, accv);
                }
                float corr = __expf(mrun - mloc);
                mrun = mloc;
                lrun *= corr;
#pragma unroll
                for (int d = 0; d < DH; d++) o[d] *= corr;
#pragma unroll
                for (int jj = 0; jj < 16; jj++) {
                    float p = __expf(s[jj] - mrun);
                    lrun += p;
                    const float4* vp = (const float4*)&Vs[cch * 16 + jj][0];
#pragma unroll
                    for (int d4 = 0; d4 < 16; d4++) {
                        float4 vv = vp[d4];
                        o[d4 * 4 + 0] = fmaf(p, vv.x, o[d4 * 4 + 0]);
                        o[d4 * 4 + 1] = fmaf(p, vv.y, o[d4 * 4 + 1]);
                        o[d4 * 4 + 2] = fmaf(p, vv.z, o[d4 * 4 + 2]);
                        o[d4 * 4 + 3] = fmaf(p, vv.w, o[d4 * 4 + 3]);
                    }
                }
            }
        }
        __syncthreads();
    }

    float inv = 1.f / lrun;
    float* op = d_attn + ((size_t)(b * Sn + qrow)) * Dn + h * DH;
#pragma unroll
    for (int d4 = 0; d4 < 16; d4++) {
        float4 v = make_float4(o[d4 * 4 + 0] * inv, o[d4 * 4 + 1] * inv,
                               o[d4 * 4 + 2] * inv, o[d4 * 4 + 3] * inv);
        *(float4*)(op + d4 * 4) = v;
    }
}

// ---------------------------------------------------------------------------
// Host launch
// ---------------------------------------------------------------------------
extern "C" void kernel_launch(void* const* d_in, const int* in_sizes, int n_in,
                              void* d_out, int out_size)
{
    const float* x    = (const float*)d_in[0];
    const float* qk_f = (const float*)d_in[1];
    const float* qk_r = (const float*)d_in[2];
    const float* v_f  = (const float*)d_in[3];
    const float* v_r  = (const float*)d_in[4];
    const float* Wgq  = (const float*)d_in[5];
    const float* Wgk  = (const float*)d_in[6];
    const float* Wgv  = (const float*)d_in[7];
    const float* W_O  = (const float*)d_in[8];
    float* out = (float*)d_out;

    float *wg, *logits, *allhqk, *allhv, *aeffqk, *aeffv, *QK, *Vb, *attn;
    cudaGetSymbolAddress((void**)&wg,     d_Wg);
    cudaGetSymbolAddress((void**)&logits, d_logits);
    cudaGetSymbolAddress((void**)&allhqk, d_allh_qk);
    cudaGetSymbolAddress((void**)&allhv,  d_allh_v);
    cudaGetSymbolAddress((void**)&aeffqk, d_aeffqk);
    cudaGetSymbolAddress((void**)&aeffv,  d_aeffv);
    cudaGetSymbolAddress((void**)&QK,     d_QK);
    cudaGetSymbolAddress((void**)&Vb,     d_Vb);
    cudaGetSymbolAddress((void**)&attn,   d_attn);

    dim3 t256(256);

    // 0) Pack gate weights
    pack_wg<<<(Dn * NNEUR) / 256, 256>>>(Wgq, Wgk, Wgv);

    // 1) Router logits: [2048,768] = x @ Wg
    tf32_gemm<<<dim3(NG / 128, BS / 128, 1), t256>>>(
        x, wg, logits, Dn, Dn, NG, NG, 0, 0, 0);

    // 2) Softmax + group -> gates
    gate_kernel<<<dim3(BS, 3), 256>>>();

    // 3) Features: all_h[bs,m,r] = x @ {qk_f,v_f}[m]  (batched over m)
    tf32_gemm<<<dim3(1, BS / 128, Mn), t256>>>(
        x, qk_f, allhqk, Dn, Dn, Rn, Mn * Rn, 0, (long long)Dn * Rn, Rn);
    tf32_gemm<<<dim3(1, BS / 128, Mn), t256>>>(
        x, v_f, allhv, Dn, Dn, Rn, Mn * Rn, 0, (long long)Dn * Rn, Rn);

    // 4) Weighted mix -> hQ, hK, hV
    mix_kernel<<<BS, 128>>>();

    // 5) Aeff for Q,K,V
    aeff3_kernel<<<BS, 256>>>();

    // 6) Restore: Q,K batched (shared B = qk_r); V separate
    tf32_gemm<<<dim3(Dn / 128, BS / 128, 2), t256>>>(
        aeffqk, qk_r, QK, Mn * Rn, Mn * Rn, Dn, Dn,
        (long long)BS * (Mn * Rn), 0, (long long)BS * Dn);
    tf32_gemm<<<dim3(Dn / 128, BS / 128, 1), t256>>>(
        aeffv, v_r, Vb, Mn * Rn, Mn * Rn, Dn, Dn, 0, 0, 0);

    // 7) Causal multi-head attention
    flash_kernel<<<dim3(Sn / 128, Bn * NH), 128>>>();

    // 8) Output projection -> d_out
    tf32_gemm<<<dim3(Dn / 128, BS / 128, 1), t256>>>(
        attn, W_O, out, Dn, Dn, Dn, Dn, 0, 0, 0);
}

// round 4
// speedup vs baseline: 4.9814x; 1.8723x over previous
#include <cuda_runtime.h>
#include <math.h>
#include <stdint.h>

// ---------------------------------------------------------------------------
// Problem constants
// ---------------------------------------------------------------------------
#define Bn  2
#define Sn  1024
#define Dn  1024
#define Mn  8
#define Rn  128
#define NNEUR 256
#define NH  16
#define DH  64
#define BS  (Bn * Sn)          // 2048 tokens
#define NG  768                // packed gate width (3*256)
#define MR  (Mn * Rn)          // 1024

// ---------------------------------------------------------------------------
// Device scratch (allocation-free: __device__ globals)
// ---------------------------------------------------------------------------
__device__ float d_Wg[Dn * NG];                // packed [Wg_q | Wg_k | Wg_v]
__device__ float d_logits[BS * NG];            // router logits, [token][768]
__device__ float d_g[3 * BS * Mn];             // grouped gates (q,k,v)
__device__ float d_allh[2 * BS * MR];          // [qk ; v] features
__device__ float d_hq[BS * Rn];
__device__ float d_hk[BS * Rn];
__device__ float d_hv[BS * Rn];
__device__ float d_aeff3[3 * BS * MR];         // (g⊗h) for Q,K,V
__device__ float d_QKV[3 * BS * Dn];           // Q ; K ; V
__device__ float d_attn[BS * Dn];

// ---------------------------------------------------------------------------
// TF32 helpers
// ---------------------------------------------------------------------------
__device__ __forceinline__ float to_tf32(float x) {
    uint32_t u;
    asm("cvt.rna.tf32.f32 %0, %1;" : "=r"(u) : "f"(x));
    return __uint_as_float(u);
}

__device__ __forceinline__ void mma_tf32(float c[4], const uint32_t a[4],
                                         uint32_t b0, uint32_t b1) {
    asm volatile(
        "mma.sync.aligned.m16n8k8.row.col.f32.tf32.tf32.f32 "
        "{%0,%1,%2,%3}, {%4,%5,%6,%7}, {%8,%9}, {%0,%1,%2,%3};\n"
        : "+f"(c[0]), "+f"(c[1]), "+f"(c[2]), "+f"(c[3])
        : "r"(a[0]), "r"(a[1]), "r"(a[2]), "r"(a[3]), "r"(b0), "r"(b1));
}

// ---------------------------------------------------------------------------
// TF32 tensor-core GEMM body: C = A @ B (row-major).
// BM=BN=128, BK=16, 256 threads (8 warps, warp tile 64x32),
// double-buffered smem, conflict-free fragment LDS (row stride 136).
// ---------------------------------------------------------------------------
__device__ __forceinline__ void
tf32_gemm_body(const float* __restrict__ A, const float* __restrict__ B,
               float* __restrict__ C, int Kdim, int lda, int ldb, int ldc)
{
    __shared__ float As[2][16][136];
    __shared__ float Bs[2][16][136];

    const int tid  = threadIdx.x;
    const int brow = blockIdx.y * 128;
    const int bcol = blockIdx.x * 128;

    const int warp = tid >> 5;
    const int lane = tid & 31;
    const int wm   = warp >> 2;
    const int wn   = warp & 3;
    const int grp  = lane >> 2;
    const int tg   = lane & 3;

    const int aRow0 = tid >> 2;
    const int aC4   = (tid & 3) << 2;
    const int bK0   = tid >> 5;
    const int bN4   = (tid & 31) << 2;

    const float* Ap0 = A + (size_t)(brow + aRow0) * lda + aC4;
    const float* Ap1 = A + (size_t)(brow + aRow0 + 64) * lda + aC4;
    const float* Bp0 = B + (size_t)bK0 * ldb + bcol + bN4;
    const float* Bp1 = B + (size_t)(bK0 + 8) * ldb + bcol + bN4;

    float c[4][4][4];
#pragma unroll
    for (int i = 0; i < 4; i++)
#pragma unroll
        for (int j = 0; j < 4; j++)
#pragma unroll
            for (int r = 0; r < 4; r++) c[i][j][r] = 0.f;

    const int kTiles = Kdim >> 4;

    {
        float4 a0 = *(const float4*)Ap0;
        float4 a1 = *(const float4*)Ap1;
        float4 b0 = *(const float4*)Bp0;
        float4 b1 = *(const float4*)Bp1;
        As[0][aC4 + 0][aRow0] = to_tf32(a0.x);
        As[0][aC4 + 1][aRow0] = to_tf32(a0.y);
        As[0][aC4 + 2][aRow0] = to_tf32(a0.z);
        As[0][aC4 + 3][aRow0] = to_tf32(a0.w);
        As[0][aC4 + 0][aRow0 + 64] = to_tf32(a1.x);
        As[0][aC4 + 1][aRow0 + 64] = to_tf32(a1.y);
        As[0][aC4 + 2][aRow0 + 64] = to_tf32(a1.z);
        As[0][aC4 + 3][aRow0 + 64] = to_tf32(a1.w);
        float4 tb0 = make_float4(to_tf32(b0.x), to_tf32(b0.y), to_tf32(b0.z), to_tf32(b0.w));
        float4 tb1 = make_float4(to_tf32(b1.x), to_tf32(b1.y), to_tf32(b1.z), to_tf32(b1.w));
        *(float4*)&Bs[0][bK0][bN4]     = tb0;
        *(float4*)&Bs[0][bK0 + 8][bN4] = tb1;
    }
    __syncthreads();

    for (int t = 0; t < kTiles; t++) {
        const int buf = t & 1;

        float4 pa0, pa1, pb0, pb1;
        if (t + 1 < kTiles) {
            const int ko = (t + 1) << 4;
            pa0 = *(const float4*)(Ap0 + ko);
            pa1 = *(const float4*)(Ap1 + ko);
            pb0 = *(const float4*)(Bp0 + (size_t)ko * ldb);
            pb1 = *(const float4*)(Bp1 + (size_t)ko * ldb);
        }

#pragma unroll
        for (int ks = 0; ks < 2; ks++) {
            const int kb = ks << 3;
            uint32_t af[4][4], bf[4][2];
#pragma unroll
            for (int i = 0; i < 4; i++) {
                const int m0 = wm * 64 + i * 16 + grp;
                af[i][0] = __float_as_uint(As[buf][kb + tg][m0]);
                af[i][1] = __float_as_uint(As[buf][kb + tg][m0 + 8]);
                af[i][2] = __float_as_uint(As[buf][kb + tg + 4][m0]);
                af[i][3] = __float_as_uint(As[buf][kb + tg + 4][m0 + 8]);
            }
#pragma unroll
            for (int j = 0; j < 4; j++) {
                const int n0 = wn * 32 + j * 8 + grp;
                bf[j][0] = __float_as_uint(Bs[buf][kb + tg][n0]);
                bf[j][1] = __float_as_uint(Bs[buf][kb + tg + 4][n0]);
            }
#pragma unroll
            for (int i = 0; i < 4; i++)
#pragma unroll
                for (int j = 0; j < 4; j++)
                    mma_tf32(c[i][j], af[i], bf[j][0], bf[j][1]);
        }

        if (t + 1 < kTiles) {
            const int nb = buf ^ 1;
            As[nb][aC4 + 0][aRow0] = to_tf32(pa0.x);
            As[nb][aC4 + 1][aRow0] = to_tf32(pa0.y);
            As[nb][aC4 + 2][aRow0] = to_tf32(pa0.z);
            As[nb][aC4 + 3][aRow0] = to_tf32(pa0.w);
            As[nb][aC4 + 0][aRow0 + 64] = to_tf32(pa1.x);
            As[nb][aC4 + 1][aRow0 + 64] = to_tf32(pa1.y);
            As[nb][aC4 + 2][aRow0 + 64] = to_tf32(pa1.z);
            As[nb][aC4 + 3][aRow0 + 64] = to_tf32(pa1.w);
            float4 tb0 = make_float4(to_tf32(pb0.x), to_tf32(pb0.y), to_tf32(pb0.z), to_tf32(pb0.w));
            float4 tb1 = make_float4(to_tf32(pb1.x), to_tf32(pb1.y), to_tf32(pb1.z), to_tf32(pb1.w));
            *(float4*)&Bs[nb][bK0][bN4]     = tb0;
            *(float4*)&Bs[nb][bK0 + 8][bN4] = tb1;
        }
        __syncthreads();
    }

#pragma unroll
    for (int i = 0; i < 4; i++) {
        const int r0 = brow + wm * 64 + i * 16 + grp;
#pragma unroll
        for (int j = 0; j < 4; j++) {
            const int cc = bcol + wn * 32 + j * 8 + tg * 2;
            *(float2*)&C[(size_t)r0 * ldc + cc]       = make_float2(c[i][j][0], c[i][j][1]);
            *(float2*)&C[(size_t)(r0 + 8) * ldc + cc] = make_float2(c[i][j][2], c[i][j][3]);
        }
    }
}

// -------- GEMM wrappers --------------------------------------------------
__global__ void __launch_bounds__(256, 2)
gemm_generic(const float* __restrict__ A, const float* __restrict__ B,
             float* __restrict__ C, int Kdim, int lda, int ldb, int ldc)
{
    tf32_gemm_body(A, B, C, Kdim, lda, ldb, ldc);
}

// features: z 0..15 -> (qk_f batches 0-7, v_f batches 0-7)
__global__ void __launch_bounds__(256, 2)
gemm_feat(const float* __restrict__ x, const float* __restrict__ qkf,
          const float* __restrict__ vf)
{
    const int z = blockIdx.z;
    const float* B = (z < 8) ? qkf + (size_t)z * Dn * Rn
                             : vf  + (size_t)(z - 8) * Dn * Rn;
    float* C = d_allh + (z < 8 ? 0 : (size_t)BS * MR) + (size_t)(z & 7) * Rn;
    tf32_gemm_body(x, B, C, Dn, Dn, Rn, MR);
}

// restore: z 0..2 -> Q (qk_r), K (qk_r), V (v_r)
__global__ void __launch_bounds__(256, 2)
gemm_restore(const float* __restrict__ qk_r, const float* __restrict__ v_r)
{
    const int z = blockIdx.z;
    const float* A = d_aeff3 + (size_t)z * BS * MR;
    const float* B = (z < 2) ? qk_r : v_r;
    float* C = d_QKV + (size_t)z * BS * Dn;
    tf32_gemm_body(A, B, C, MR, MR, Dn, Dn);
}

// ---------------------------------------------------------------------------
// Pack Wg_q/k/v -> d_Wg [D][768]
// ---------------------------------------------------------------------------
__global__ void pack_wg(const float* __restrict__ q, const float* __restrict__ k,
                        const float* __restrict__ v)
{
    const int idx = blockIdx.x * 256 + threadIdx.x;
    const int d = idx >> 8;
    const int n = idx & 255;
    d_Wg[(size_t)d * NG + n]       = q[idx];
    d_Wg[(size_t)d * NG + 256 + n] = k[idx];
    d_Wg[(size_t)d * NG + 512 + n] = v[idx];
}

// ---------------------------------------------------------------------------
// Gate softmax + grouping. grid=(BS,3), block=256.
// ---------------------------------------------------------------------------
__global__ void gate_kernel()
{
    const int token = blockIdx.x;
    const int which = blockIdx.y;
    const float* lp = d_logits + (size_t)token * NG + which * NNEUR;
    const int t = threadIdx.x;

    __shared__ float red[256];
    __shared__ float gs[8];

    float v = lp[t];
    red[t] = v; __syncthreads();
#pragma unroll
    for (int s = 128; s > 0; s >>= 1) {
        if (t < s) red[t] = fmaxf(red[t], red[t + s]);
        __syncthreads();
    }
    float mx = red[0];
    __syncthreads();

    float e = __expf(v - mx);
#pragma unroll
    for (int off = 16; off; off >>= 1)
        e += __shfl_down_sync(0xffffffffu, e, off);
    if ((t & 31) == 0) gs[t >> 5] = e;
    __syncthreads();

    if (t < 8) {
        float tot = 0.f;
#pragma unroll
        for (int i = 0; i < 8; i++) tot += gs[i];
        d_g[((size_t)which * BS + token) * Mn + t] = gs[t] / (tot * (1.0f + 1e-8f));
    }
}

// ---------------------------------------------------------------------------
// Mix: h[bs,r] = sum_m g[bs,m] * all_h[bs,m,r]
// ---------------------------------------------------------------------------
__global__ void mix_kernel()
{
    const int bs = blockIdx.x;
    const int r  = threadIdx.x;
    const float* gq = d_g + (size_t)bs * Mn;
    const float* gk = d_g + (size_t)BS * Mn + (size_t)bs * Mn;
    const float* gv = d_g + (size_t)2 * BS * Mn + (size_t)bs * Mn;

    float hq = 0.f, hk = 0.f, hv = 0.f;
#pragma unroll
    for (int m = 0; m < Mn; m++) {
        float a  = d_allh[(size_t)bs * MR + m * Rn + r];
        float av = d_allh[(size_t)BS * MR + (size_t)bs * MR + m * Rn + r];
        hq = fmaf(gq[m], a, hq);
        hk = fmaf(gk[m], a, hk);
        hv = fmaf(gv[m], av, hv);
    }
    d_hq[bs * Rn + r] = hq;
    d_hk[bs * Rn + r] = hk;
    d_hv[bs * Rn + r] = hv;
}

// ---------------------------------------------------------------------------
// Aeff3[z=0/1/2][bs, m*R+r] = g_z[bs,m]*h_z[bs,r]
// ---------------------------------------------------------------------------
__global__ void aeff3_kernel()
{
    const int bs = blockIdx.x;
    const int cidx = threadIdx.x * 4;
    const int m = cidx >> 7;

    const float gq = d_g[(size_t)bs * Mn + m];
    const float gk = d_g[(size_t)BS * Mn + (size_t)bs * Mn + m];
    const float gv = d_g[(size_t)2 * BS * Mn + (size_t)bs * Mn + m];

    const int r = cidx & 127;
    float4 hq4 = *(const float4*)(d_hq + (size_t)bs * Rn + r);
    float4 hk4 = *(const float4*)(d_hk + (size_t)bs * Rn + r);
    float4 hv4 = *(const float4*)(d_hv + (size_t)bs * Rn + r);

    *(float4*)(d_aeff3 + (size_t)bs * MR + cidx) =
        make_float4(gq * hq4.x, gq * hq4.y, gq * hq4.z, gq * hq4.w);
    *(float4*)(d_aeff3 + (size_t)BS * MR + (size_t)bs * MR + cidx) =
        make_float4(gk * hk4.x, gk * hk4.y, gk * hk4.z, gk * hk4.w);
    *(float4*)(d_aeff3 + (size_t)2 * BS * MR + (size_t)bs * MR + cidx) =
        make_float4(gv * hv4.x, gv * hv4.y, gv * hv4.z, gv * hv4.w);
}

// ---------------------------------------------------------------------------
// Tensor-core causal flash attention (TF32 m16n8k8).
// Block: 128 threads (4 warps), 64 query rows, head dim 64.
// Grid: (S/64, B*NH) = (16, 32).
// Ks stride 68 (banks 4*grp+tg, conflict-free for [row=grp][col=tg] reads),
// Vs stride 72 (banks 8*tg+grp, conflict-free for [row=tg][col=grp] reads).
// ---------------------------------------------------------------------------
__global__ void __launch_bounds__(128, 3)
flash_mma_kernel()
{
    __shared__ float Ks[64][68];
    __shared__ float Vs[64][72];

    const int tid  = threadIdx.x;
    const int warp = tid >> 5;
    const int lane = tid & 31;
    const int grp  = lane >> 2;
    const int tg   = lane & 3;
    const int qb   = blockIdx.x;
    const int bh   = blockIdx.y;
    const int b    = bh >> 4;
    const int h    = bh & 15;
    const int q0   = qb * 64;
    const int m0   = warp * 16;

    const float* Qg = d_QKV;
    const float* Kg = d_QKV + (size_t)BS * Dn;
    const float* Vg = d_QKV + (size_t)2 * BS * Dn;

    // ---- stage Q tile into Ks, build register A-fragments (pre-scaled) ----
#pragma unroll
    for (int i = 0; i < 8; i++) {
        int idx = tid + i * 128;
        int row = idx >> 4, c = (idx & 15) * 4;
        float4 v = *(const float4*)(Qg + (size_t)(b * Sn + q0 + row) * Dn + h * DH + c);
        float4 t4 = make_float4(to_tf32(v.x * 0.125f), to_tf32(v.y * 0.125f),
                                to_tf32(v.z * 0.125f), to_tf32(v.w * 0.125f));
        *(float4*)&Ks[row][c] = t4;
    }
    __syncthreads();

    uint32_t qf[8][4];
#pragma unroll
    for (int dk = 0; dk < 8; dk++) {
        qf[dk][0] = __float_as_uint(Ks[m0 + grp][dk * 8 + tg]);
        qf[dk][1] = __float_as_uint(Ks[m0 + grp + 8][dk * 8 + tg]);
        qf[dk][2] = __float_as_uint(Ks[m0 + grp][dk * 8 + tg + 4]);
        qf[dk][3] = __float_as_uint(Ks[m0 + grp + 8][dk * 8 + tg + 4]);
    }
    __syncthreads();

    float co[8][4];
#pragma unroll
    for (int j = 0; j < 8; j++)
#pragma unroll
        for (int r = 0; r < 4; r++) co[j][r] = 0.f;
    float mr0 = -1e30f, mr1 = -1e30f, l0 = 0.f, l1 = 0.f;

    for (int kt = 0; kt <= qb; kt++) {
        const int k0 = kt * 64;

        // ---- load K,V tile (with tf32 rounding) ----
#pragma unroll
        for (int i = 0; i < 8; i++) {
            int idx = tid + i * 128;
            int row = idx >> 4, c = (idx & 15) * 4;
            size_t g = (size_t)(b * Sn + k0 + row) * Dn + h * DH + c;
            float4 kv = *(const float4*)(Kg + g);
            float4 vv = *(const float4*)(Vg + g);
            *(float4*)&Ks[row][c] = make_float4(to_tf32(kv.x), to_tf32(kv.y),
                                                to_tf32(kv.z), to_tf32(kv.w));
            *(float4*)&Vs[row][c] = make_float4(to_tf32(vv.x), to_tf32(vv.y),
                                                to_tf32(vv.z), to_tf32(vv.w));
        }
        __syncthreads();

        // ---- S = Q @ K^T (scaled) ----
        float cs[8][4];
#pragma unroll
        for (int j = 0; j < 8; j++) {
#pragma unroll
            for (int r = 0; r < 4; r++) cs[j][r] = 0.f;
#pragma unroll
            for (int dk = 0; dk < 8; dk++) {
                uint32_t b0 = __float_as_uint(Ks[j * 8 + grp][dk * 8 + tg]);
                uint32_t b1 = __float_as_uint(Ks[j * 8 + grp][dk * 8 + tg + 4]);
                mma_tf32(cs[j], qf[dk], b0, b1);
            }
        }

        // ---- causal mask (diagonal tile only) ----
        if (kt == qb) {
            const int r0 = q0 + m0 + grp;
            const int r1 = r0 + 8;
#pragma unroll
            for (int j = 0; j < 8; j++) {
                const int ca = k0 + j * 8 + 2 * tg;
                if (ca > r0)     cs[j][0] = -1e30f;
                if (ca + 1 > r0) cs[j][1] = -1e30f;
                if (ca > r1)     cs[j][2] = -1e30f;
                if (ca + 1 > r1) cs[j][3] = -1e30f;
            }
        }

        // ---- online softmax ----
        float mx0 = mr0, mx1 = mr1;
#pragma unroll
        for (int j = 0; j < 8; j++) {
            mx0 = fmaxf(mx0, fmaxf(cs[j][0], cs[j][1]));
            mx1 = fmaxf(mx1, fmaxf(cs[j][2], cs[j][3]));
        }
        mx0 = fmaxf(mx0, __shfl_xor_sync(0xffffffffu, mx0, 1));
        mx0 = fmaxf(mx0, __shfl_xor_sync(0xffffffffu, mx0, 2));
        mx1 = fmaxf(mx1, __shfl_xor_sync(0xffffffffu, mx1, 1));
        mx1 = fmaxf(mx1, __shfl_xor_sync(0xffffffffu, mx1, 2));

        float corr0 = __expf(mr0 - mx0);
        float corr1 = __expf(mr1 - mx1);
        mr0 = mx0; mr1 = mx1;

        float s0 = 0.f, s1 = 0.f;
#pragma unroll
        for (int j = 0; j < 8; j++) {
            cs[j][0] = __expf(cs[j][0] - mx0); s0 += cs[j][0];
            cs[j][1] = __expf(cs[j][1] - mx0); s0 += cs[j][1];
            cs[j][2] = __expf(cs[j][2] - mx1); s1 += cs[j][2];
            cs[j][3] = __expf(cs[j][3] - mx1); s1 += cs[j][3];
        }
        s0 += __shfl_xor_sync(0xffffffffu, s0, 1);
        s0 += __shfl_xor_sync(0xffffffffu, s0, 2);
        s1 += __shfl_xor_sync(0xffffffffu, s1, 1);
        s1 += __shfl_xor_sync(0xffffffffu, s1, 2);
        l0 = l0 * corr0 + s0;
        l1 = l1 * corr1 + s1;

#pragma unroll
        for (int j = 0; j < 8; j++) {
            co[j][0] *= corr0; co[j][1] *= corr0;
            co[j][2] *= corr1; co[j][3] *= corr1;
        }

        // ---- O += P @ V : build P A-frags via intra-quad shuffles ----
        const int base = lane & ~3;
        const int s1l = base + (tg >> 1);
        const int s2l = s1l + 2;
        const bool odd = tg & 1;
#pragma unroll
        for (int kk = 0; kk < 8; kk++) {
            float v00 = __shfl_sync(0xffffffffu, cs[kk][0], s1l);
            float v01 = __shfl_sync(0xffffffffu, cs[kk][1], s1l);
            float v02 = __shfl_sync(0xffffffffu, cs[kk][0], s2l);
            float v03 = __shfl_sync(0xffffffffu, cs[kk][1], s2l);
            float v10 = __shfl_sync(0xffffffffu, cs[kk][2], s1l);
            float v11 = __shfl_sync(0xffffffffu, cs[kk][3], s1l);
            float v12 = __shfl_sync(0xffffffffu, cs[kk][2], s2l);
            float v13 = __shfl_sync(0xffffffffu, cs[kk][3], s2l);
            uint32_t ap[4];
            ap[0] = __float_as_uint(to_tf32(odd ? v01 : v00));
            ap[1] = __float_as_uint(to_tf32(odd ? v11 : v10));
            ap[2] = __float_as_uint(to_tf32(odd ? v03 : v02));
            ap[3] = __float_as_uint(to_tf32(odd ? v13 : v12));
#pragma unroll
            for (int j = 0; j < 8; j++) {
                uint32_t b0 = __float_as_uint(Vs[kk * 8 + tg][j * 8 + grp]);
                uint32_t b1 = __float_as_uint(Vs[kk * 8 + tg + 4][j * 8 + grp]);
                mma_tf32(co[j], ap, b0, b1);
            }
        }
        __syncthreads();
    }

    // ---- epilogue ----
    const float i0 = 1.f / l0;
    const float i1 = 1.f / l1;
    const int r0 = q0 + m0 + grp;
    float* op0 = d_attn + (size_t)(b * Sn + r0) * Dn + h * DH;
    float* op1 = d_attn + (size_t)(b * Sn + r0 + 8) * Dn + h * DH;
#pragma unroll
    for (int j = 0; j < 8; j++) {
        const int cc = j * 8 + 2 * tg;
        *(float2*)(op0 + cc) = make_float2(co[j][0] * i0, co[j][1] * i0);
        *(float2*)(op1 + cc) = make_float2(co[j][2] * i1, co[j][3] * i1);
    }
}

// ---------------------------------------------------------------------------
// Host launch
// ---------------------------------------------------------------------------
extern "C" void kernel_launch(void* const* d_in, const int* in_sizes, int n_in,
                              void* d_out, int out_size)
{
    const float* x    = (const float*)d_in[0];
    const float* qk_f = (const float*)d_in[1];
    const float* qk_r = (const float*)d_in[2];
    const float* v_f  = (const float*)d_in[3];
    const float* v_r  = (const float*)d_in[4];
    const float* Wgq  = (const float*)d_in[5];
    const float* Wgk  = (const float*)d_in[6];
    const float* Wgv  = (const float*)d_in[7];
    const float* W_O  = (const float*)d_in[8];
    float* out = (float*)d_out;

    float *wg, *logits, *attn;
    cudaGetSymbolAddress((void**)&wg,     d_Wg);
    cudaGetSymbolAddress((void**)&logits, d_logits);
    cudaGetSymbolAddress((void**)&attn,   d_attn);

    dim3 t256(256);

    // 0) Pack gate weights
    pack_wg<<<(Dn * NNEUR) / 256, 256>>>(Wgq, Wgk, Wgv);

    // 1) Router logits: [2048,768] = x @ Wg
    gemm_generic<<<dim3(NG / 128, BS / 128, 1), t256>>>(
        x, wg, logits, Dn, Dn, NG, NG);

    // 2) Softmax + group -> gates
    gate_kernel<<<dim3(BS, 3), 256>>>();

    // 3) Features merged: all_h = x @ {qk_f, v_f}  (z = 0..15)
    gemm_feat<<<dim3(1, BS / 128, 16), t256>>>(x, qk_f, v_f);

    // 4) Weighted mix -> hQ, hK, hV
    mix_kernel<<<BS, 128>>>();

    // 5) Aeff for Q,K,V
    aeff3_kernel<<<BS, 256>>>();

    // 6) Restore merged: Q,K,V in one launch (z = 0..2)
    gemm_restore<<<dim3(Dn / 128, BS / 128, 3), t256>>>(qk_r, v_r);

    // 7) Tensor-core causal attention
    flash_mma_kernel<<<dim3(Sn / 64, Bn * NH), 128>>>();

    // 8) Output projection -> d_out
    gemm_generic<<<dim3(Dn / 128, BS / 128, 1), t256>>>(
        attn, W_O, out, Dn, Dn, Dn, Dn);
}

// round 6
// speedup vs baseline: 5.6289x; 1.1300x over previous
#include <cuda_runtime.h>
#include <math.h>
#include <stdint.h>

// ---------------------------------------------------------------------------
// Problem constants
// ---------------------------------------------------------------------------
#define Bn  2
#define Sn  1024
#define Dn  1024
#define Mn  8
#define Rn  128
#define NNEUR 256
#define NH  16
#define DH  64
#define BS  (Bn * Sn)          // 2048 tokens
#define MR  (Mn * Rn)          // 1024
#define NF  2816               // merged feat width: 768 gate + 1024 qk + 1024 v

// GEMM smem geometry (3-stage cp.async pipeline)
#define A_STRIDE 20            // floats per A row (16 data + 4 pad)
#define B_STRIDE 136           // floats per B row (128 data + 8 pad)
#define A_STG (128 * A_STRIDE) // 2560 floats
#define B_STG (16 * B_STRIDE)  // 2176 floats
#define SMEM_BYTES ((3 * A_STG + 3 * B_STG) * 4)   // 56832

// ---------------------------------------------------------------------------
// Device scratch (allocation-free: __device__ globals)
// ---------------------------------------------------------------------------
__device__ float d_x32[BS * Dn];               // tf32-rounded x
__device__ float d_Bfeat[Dn * NF];             // [Wg_q|Wg_k|Wg_v|qk_f|v_f] tf32
__device__ float d_CF[BS * NF];                // logits(768) + allh_qk + allh_v
__device__ float d_Br[2 * MR * Dn];            // tf32 qk_r ; v_r
__device__ float d_Wo32[Dn * Dn];              // tf32 W_O
__device__ float d_g[3 * BS * Mn];             // grouped gates (q,k,v)
__device__ float d_hq[BS * Rn];
__device__ float d_hk[BS * Rn];
__device__ float d_hv[BS * Rn];
__device__ float d_aeff3[3 * BS * MR];         // (g⊗h) tf32
__device__ float d_QKV[3 * BS * Dn];           // Q ; K ; V (tf32)
__device__ float d_attn[BS * Dn];              // attention out (tf32)

// ---------------------------------------------------------------------------
// TF32 helpers
// ---------------------------------------------------------------------------
__device__ __forceinline__ float to_tf32(float x) {
    uint32_t u;
    asm("cvt.rna.tf32.f32 %0, %1;" : "=r"(u) : "f"(x));
    return __uint_as_float(u);
}

__device__ __forceinline__ void mma_tf32(float c[4], const uint32_t a[4],
                                         uint32_t b0, uint32_t b1) {
    asm volatile(
        "mma.sync.aligned.m16n8k8.row.col.f32.tf32.tf32.f32 "
        "{%0,%1,%2,%3}, {%4,%5,%6,%7}, {%8,%9}, {%0,%1,%2,%3};\n"
        : "+f"(c[0]), "+f"(c[1]), "+f"(c[2]), "+f"(c[3])
        : "r"(a[0]), "r"(a[1]), "r"(a[2]), "r"(a[3]), "r"(b0), "r"(b1));
}

#define CPA(dst, src) \
    asm volatile("cp.async.cg.shared.global [%0], [%1], 16;\n" :: "r"(dst), "l"(src))
#define CPCOMMIT() asm volatile("cp.async.commit_group;\n")
#define CPWAIT2()  asm volatile("cp.async.wait_group 2;\n")

// ---------------------------------------------------------------------------
// TF32 GEMM body, K = 1024 fixed (64 k-tiles of 16).
// BM=BN=128, 256 threads, 8 warps (warp tile 64x32), cp.async 3-stage.
// Inputs must already be tf32-rounded (hot loop does no conversion).
// ---------------------------------------------------------------------------
__device__ __forceinline__ void
gemm_ca_body(const float* __restrict__ A, const float* __restrict__ B,
             float* __restrict__ C, int lda, int ldb, int ldc, bool cvtOut)
{
    extern __shared__ float sm[];
    float* As = sm;                    // 3 stages [128][A_STRIDE]
    float* Bs = sm + 3 * A_STG;        // 3 stages [16][B_STRIDE]

    const int tid  = threadIdx.x;
    const int brow = blockIdx.y * 128;
    const int bcol = blockIdx.x * 128;

    const int warp = tid >> 5;
    const int lane = tid & 31;
    const int wm   = warp >> 2;
    const int wn   = warp & 3;
    const int grp  = lane >> 2;
    const int tg   = lane & 3;
    const int m0   = wm * 64;

    // cp.async source / dest mapping (2 x 16B chunks per thread per matrix)
    const int aRow = tid >> 2;               // 0..63
    const int aCol = (tid & 3) << 2;         // 0,4,8,12
    const float* Asrc0 = A + (size_t)(brow + aRow) * lda + aCol;
    const float* Asrc1 = Asrc0 + (size_t)64 * lda;

    const int bRow = tid >> 5;               // 0..7
    const int bCol = (tid & 31) << 2;        // 0..124
    const float* Bsrc0 = B + (size_t)bRow * ldb + bcol + bCol;
    const float* Bsrc1 = Bsrc0 + (size_t)8 * ldb;

    const uint32_t aBase = (uint32_t)__cvta_generic_to_shared(As);
    const uint32_t bBase = (uint32_t)__cvta_generic_to_shared(Bs);
    const uint32_t sA0 = aBase + (uint32_t)(aRow * A_STRIDE + aCol) * 4;
    const uint32_t sA1 = sA0 + 64 * A_STRIDE * 4;
    const uint32_t sB0 = bBase + (uint32_t)(bRow * B_STRIDE + bCol) * 4;
    const uint32_t sB1 = sB0 + 8 * B_STRIDE * 4;

#define ISSUE(s_, t_) do {                                        \
        const uint32_t oa = (uint32_t)(s_) * (A_STG * 4);          \
        const uint32_t ob = (uint32_t)(s_) * (B_STG * 4);          \
        CPA(sA0 + oa, Asrc0 + ((t_) << 4));                        \
        CPA(sA1 + oa, Asrc1 + ((t_) << 4));                        \
        CPA(sB0 + ob, Bsrc0 + (size_t)((t_) << 4) * ldb);          \
        CPA(sB1 + ob, Bsrc1 + (size_t)((t_) << 4) * ldb);          \
        CPCOMMIT(); } while (0)

    float c[4][4][4];
#pragma unroll
    for (int i = 0; i < 4; i++)
#pragma unroll
        for (int j = 0; j < 4; j++)
#pragma unroll
            for (int r = 0; r < 4; r++) c[i][j][r] = 0.f;

    ISSUE(0, 0);
    ISSUE(1, 1);
    ISSUE(2, 2);

    for (int t = 0; t < 64; t++) {
        const int s = t % 3;
        CPWAIT2();
        __syncthreads();

        const float* Ast = As + s * A_STG;
        const float* Bst = Bs + s * B_STG;

#pragma unroll
        for (int ks = 0; ks < 2; ks++) {
            const int kb = ks << 3;
            uint32_t af[4][4], bf[4][2];
#pragma unroll
            for (int i = 0; i < 4; i++) {
                const int r0 = (m0 + i * 16 + grp) * A_STRIDE;
                af[i][0] = __float_as_uint(Ast[r0 + kb + tg]);
                af[i][1] = __float_as_uint(Ast[r0 + 8 * A_STRIDE + kb + tg]);
                af[i][2] = __float_as_uint(Ast[r0 + kb + tg + 4]);
                af[i][3] = __float_as_uint(Ast[r0 + 8 * A_STRIDE + kb + tg + 4]);
            }
#pragma unroll
            for (int j = 0; j < 4; j++) {
                const int n0 = wn * 32 + j * 8 + grp;
                bf[j][0] = __float_as_uint(Bst[(kb + tg) * B_STRIDE + n0]);
                bf[j][1] = __float_as_uint(Bst[(kb + tg + 4) * B_STRIDE + n0]);
            }
#pragma unroll
            for (int i = 0; i < 4; i++)
#pragma unroll
                for (int j = 0; j < 4; j++)
                    mma_tf32(c[i][j], af[i], bf[j][0], bf[j][1]);
        }

        __syncthreads();
        if (t + 3 < 64) ISSUE(s, t + 3); else CPCOMMIT();
    }
#undef ISSUE

#pragma unroll
    for (int i = 0; i < 4; i++) {
        const int r0 = brow + m0 + i * 16 + grp;
#pragma unroll
        for (int j = 0; j < 4; j++) {
            const int cc = bcol + wn * 32 + j * 8 + tg * 2;
            float v0 = c[i][j][0], v1 = c[i][j][1], v2 = c[i][j][2], v3 = c[i][j][3];
            if (cvtOut) {
                v0 = to_tf32(v0); v1 = to_tf32(v1);
                v2 = to_tf32(v2); v3 = to_tf32(v3);
            }
            *(float2*)&C[(size_t)r0 * ldc + cc]       = make_float2(v0, v1);
            *(float2*)&C[(size_t)(r0 + 8) * ldc + cc] = make_float2(v2, v3);
        }
    }
}

// -------- GEMM wrappers ----------------------------------------------------
__global__ void __launch_bounds__(256, 2)
gemm_ca(const float* __restrict__ A, const float* __restrict__ B,
        float* __restrict__ C, int lda, int ldb, int ldc, int cvtOut)
{
    gemm_ca_body(A, B, C, lda, ldb, ldc, cvtOut != 0);
}

// restore: z 0..2 -> Q (qk_r), K (qk_r), V (v_r); outputs tf32-rounded
__global__ void __launch_bounds__(256, 2)
gemm_restore_ca()
{
    const int z = blockIdx.z;
    const float* A = d_aeff3 + (size_t)z * BS * MR;
    const float* B = d_Br + (z < 2 ? 0 : (size_t)MR * Dn);
    float* C = d_QKV + (size_t)z * BS * Dn;
    gemm_ca_body(A, B, C, MR, Dn, Dn, true);
}

// ---------------------------------------------------------------------------
// pack_misc: tf32-round x, qk_r, v_r, W_O (float4 per thread)
// ---------------------------------------------------------------------------
#define X_ELEMS  (BS * Dn)          // 2097152
#define R_ELEMS  (MR * Dn)          // 1048576
__global__ void pack_misc(const float* __restrict__ x, const float* __restrict__ qk_r,
                          const float* __restrict__ v_r, const float* __restrict__ wo)
{
    const size_t i4 = ((size_t)blockIdx.x * 256 + threadIdx.x) * 4;
    const float* src;
    float* dst;
    size_t off;
    if (i4 < X_ELEMS)                     { src = x;    dst = d_x32;            off = i4; }
    else if (i4 < X_ELEMS + R_ELEMS)      { src = qk_r; dst = d_Br;             off = i4 - X_ELEMS; }
    else if (i4 < X_ELEMS + 2 * R_ELEMS)  { src = v_r;  dst = d_Br + R_ELEMS;   off = i4 - X_ELEMS - R_ELEMS; }
    else                                  { src = wo;   dst = d_Wo32;           off = i4 - X_ELEMS - 2 * R_ELEMS; }
    float4 v = *(const float4*)(src + off);
    *(float4*)(dst + off) = make_float4(to_tf32(v.x), to_tf32(v.y),
                                        to_tf32(v.z), to_tf32(v.w));
}

// ---------------------------------------------------------------------------
// pack_bfeat: build [D][2816] = [Wg_q|Wg_k|Wg_v|qk_f(m-major cols)|v_f]
// ---------------------------------------------------------------------------
__global__ void pack_bfeat(const float* __restrict__ wq, const float* __restrict__ wk,
                           const float* __restrict__ wv, const float* __restrict__ qkf,
                           const float* __restrict__ vf)
{
    const int d = blockIdx.x;
    for (int col = threadIdx.x; col < NF; col += 256) {
        float v;
        if (col < 768) {
            const int which = col >> 8;
            const int n = col & 255;
            const float* w = (which == 0) ? wq : (which == 1) ? wk : wv;
            v = w[(size_t)d * NNEUR + n];
        } else if (col < 1792) {
            const int cc = col - 768;
            v = qkf[((size_t)(cc >> 7) * Dn + d) * Rn + (cc & 127)];
        } else {
            const int cc = col - 1792;
            v = vf[((size_t)(cc >> 7) * Dn + d) * Rn + (cc & 127)];
        }
        d_Bfeat[(size_t)d * NF + col] = to_tf32(v);
    }
}

// ---------------------------------------------------------------------------
// Gate softmax + grouping. Reads logits from d_CF (stride NF). grid=(BS,3).
// ---------------------------------------------------------------------------
__global__ void gate_kernel()
{
    const int token = blockIdx.x;
    const int which = blockIdx.y;
    const float* lp = d_CF + (size_t)token * NF + which * NNEUR;
    const int t = threadIdx.x;

    __shared__ float red[256];
    __shared__ float gs[8];

    float v = lp[t];
    red[t] = v; __syncthreads();
#pragma unroll
    for (int s = 128; s > 0; s >>= 1) {
        if (t < s) red[t] = fmaxf(red[t], red[t + s]);
        __syncthreads();
    }
    float mx = red[0];
    __syncthreads();

    float e = __expf(v - mx);
#pragma unroll
    for (int off = 16; off; off >>= 1)
        e += __shfl_down_sync(0xffffffffu, e, off);
    if ((t & 31) == 0) gs[t >> 5] = e;
    __syncthreads();

    if (t < 8) {
        float tot = 0.f;
#pragma unroll
        for (int i = 0; i < 8; i++) tot += gs[i];
        d_g[((size_t)which * BS + token) * Mn + t] = gs[t] / (tot * (1.0f + 1e-8f));
    }
}

// ---------------------------------------------------------------------------
// Mix: h[bs,r] = sum_m g[bs,m] * allh[bs,m,r]  (allh lives in d_CF cols 768+)
// ---------------------------------------------------------------------------
__global__ void mix_kernel()
{
    const int bs = blockIdx.x;
    const int r  = threadIdx.x;
    const float* gq = d_g + (size_t)bs * Mn;
    const float* gk = d_g + (size_t)BS * Mn + (size_t)bs * Mn;
    const float* gv = d_g + (size_t)2 * BS * Mn + (size_t)bs * Mn;
    const float* row = d_CF + (size_t)bs * NF;

    float hq = 0.f, hk = 0.f, hv = 0.f;
#pragma unroll
    for (int m = 0; m < Mn; m++) {
        float a  = row[768 + m * Rn + r];
        float av = row[1792 + m * Rn + r];
        hq = fmaf(gq[m], a, hq);
        hk = fmaf(gk[m], a, hk);
        hv = fmaf(gv[m], av, hv);
    }
    d_hq[bs * Rn + r] = hq;
    d_hk[bs * Rn + r] = hk;
    d_hv[bs * Rn + r] = hv;
}

// ---------------------------------------------------------------------------
// Aeff3[z][bs, m*R+r] = tf32(g_z[bs,m]*h_z[bs,r])
// ---------------------------------------------------------------------------
__global__ void aeff3_kernel()
{
    const int bs = blockIdx.x;
    const int cidx = threadIdx.x * 4;
    const int m = cidx >> 7;

    const float gq = d_g[(size_t)bs * Mn + m];
    const float gk = d_g[(size_t)BS * Mn + (size_t)bs * Mn + m];
    const float gv = d_g[(size_t)2 * BS * Mn + (size_t)bs * Mn + m];

    const int r = cidx & 127;
    float4 hq4 = *(const float4*)(d_hq + (size_t)bs * Rn + r);
    float4 hk4 = *(const float4*)(d_hk + (size_t)bs * Rn + r);
    float4 hv4 = *(const float4*)(d_hv + (size_t)bs * Rn + r);

    *(float4*)(d_aeff3 + (size_t)bs * MR + cidx) =
        make_float4(to_tf32(gq * hq4.x), to_tf32(gq * hq4.y),
                    to_tf32(gq * hq4.z), to_tf32(gq * hq4.w));
    *(float4*)(d_aeff3 + (size_t)BS * MR + (size_t)bs * MR + cidx) =
        make_float4(to_tf32(gk * hk4.x), to_tf32(gk * hk4.y),
                    to_tf32(gk * hk4.z), to_tf32(gk * hk4.w));
    *(float4*)(d_aeff3 + (size_t)2 * BS * MR + (size_t)bs * MR + cidx) =
        make_float4(to_tf32(gv * hv4.x), to_tf32(gv * hv4.y),
                    to_tf32(gv * hv4.z), to_tf32(gv * hv4.w));
}

// ---------------------------------------------------------------------------
// Tensor-core causal flash attention (TF32 m16n8k8). Q/K/V pre-rounded.
// Block 128 threads (4 warps), 64 query rows. Grid (S/64, B*NH).
// ---------------------------------------------------------------------------
__global__ void __launch_bounds__(128, 3)
flash_mma_kernel()
{
    __shared__ float Ks[64][68];
    __shared__ float Vs[64][72];

    const int tid  = threadIdx.x;
    const int warp = tid >> 5;
    const int lane = tid & 31;
    const int grp  = lane >> 2;
    const int tg   = lane & 3;
    const int qb   = blockIdx.x;
    const int bh   = blockIdx.y;
    const int b    = bh >> 4;
    const int h    = bh & 15;
    const int q0   = qb * 64;
    const int m0   = warp * 16;

    const float* Qg = d_QKV;
    const float* Kg = d_QKV + (size_t)BS * Dn;
    const float* Vg = d_QKV + (size_t)2 * BS * Dn;

    // stage Q tile (scale by 1/8 — exact power of two, stays tf32)
#pragma unroll
    for (int i = 0; i < 8; i++) {
        int idx = tid + i * 128;
        int row = idx >> 4, c = (idx & 15) * 4;
        float4 v = *(const float4*)(Qg + (size_t)(b * Sn + q0 + row) * Dn + h * DH + c);
        *(float4*)&Ks[row][c] = make_float4(v.x * 0.125f, v.y * 0.125f,
                                            v.z * 0.125f, v.w * 0.125f);
    }
    __syncthreads();

    uint32_t qf[8][4];
#pragma unroll
    for (int dk = 0; dk < 8; dk++) {
        qf[dk][0] = __float_as_uint(Ks[m0 + grp][dk * 8 + tg]);
        qf[dk][1] = __float_as_uint(Ks[m0 + grp + 8][dk * 8 + tg]);
        qf[dk][2] = __float_as_uint(Ks[m0 + grp][dk * 8 + tg + 4]);
        qf[dk][3] = __float_as_uint(Ks[m0 + grp + 8][dk * 8 + tg + 4]);
    }
    __syncthreads();

    float co[8][4];
#pragma unroll
    for (int j = 0; j < 8; j++)
#pragma unroll
        for (int r = 0; r < 4; r++) co[j][r] = 0.f;
    float mr0 = -1e30f, mr1 = -1e30f, l0 = 0.f, l1 = 0.f;

    for (int kt = 0; kt <= qb; kt++) {
        const int k0 = kt * 64;

#pragma unroll
        for (int i = 0; i < 8; i++) {
            int idx = tid + i * 128;
            int row = idx >> 4, c = (idx & 15) * 4;
            size_t g = (size_t)(b * Sn + k0 + row) * Dn + h * DH + c;
            *(float4*)&Ks[row][c] = *(const float4*)(Kg + g);
            *(float4*)&Vs[row][c] = *(const float4*)(Vg + g);
        }
        __syncthreads();

        float cs[8][4];
#pragma unroll
        for (int j = 0; j < 8; j++) {
#pragma unroll
            for (int r = 0; r < 4; r++) cs[j][r] = 0.f;
#pragma unroll
            for (int dk = 0; dk < 8; dk++) {
                uint32_t b0 = __float_as_uint(Ks[j * 8 + grp][dk * 8 + tg]);
                uint32_t b1 = __float_as_uint(Ks[j * 8 + grp][dk * 8 + tg + 4]);
                mma_tf32(cs[j], qf[dk], b0, b1);
            }
        }

        if (kt == qb) {
            const int r0 = q0 + m0 + grp;
            const int r1 = r0 + 8;
#pragma unroll
            for (int j = 0; j < 8; j++) {
                const int ca = k0 + j * 8 + 2 * tg;
                if (ca > r0)     cs[j][0] = -1e30f;
                if (ca + 1 > r0) cs[j][1] = -1e30f;
                if (ca > r1)     cs[j][2] = -1e30f;
                if (ca + 1 > r1) cs[j][3] = -1e30f;
            }
        }

        float mx0 = mr0, mx1 = mr1;
#pragma unroll
        for (int j = 0; j < 8; j++) {
            mx0 = fmaxf(mx0, fmaxf(cs[j][0], cs[j][1]));
            mx1 = fmaxf(mx1, fmaxf(cs[j][2], cs[j][3]));
        }
        mx0 = fmaxf(mx0, __shfl_xor_sync(0xffffffffu, mx0, 1));
        mx0 = fmaxf(mx0, __shfl_xor_sync(0xffffffffu, mx0, 2));
        mx1 = fmaxf(mx1, __shfl_xor_sync(0xffffffffu, mx1, 1));
        mx1 = fmaxf(mx1, __shfl_xor_sync(0xffffffffu, mx1, 2));

        float corr0 = __expf(mr0 - mx0);
        float corr1 = __expf(mr1 - mx1);
        mr0 = mx0; mr1 = mx1;

        float s0 = 0.f, s1 = 0.f;
#pragma unroll
        for (int j = 0; j < 8; j++) {
            cs[j][0] = __expf(cs[j][0] - mx0); s0 += cs[j][0];
            cs[j][1] = __expf(cs[j][1] - mx0); s0 += cs[j][1];
            cs[j][2] = __expf(cs[j][2] - mx1); s1 += cs[j][2];
            cs[j][3] = __expf(cs[j][3] - mx1); s1 += cs[j][3];
        }
        s0 += __shfl_xor_sync(0xffffffffu, s0, 1);
        s0 += __shfl_xor_sync(0xffffffffu, s0, 2);
        s1 += __shfl_xor_sync(0xffffffffu, s1, 1);
        s1 += __shfl_xor_sync(0xffffffffu, s1, 2);
        l0 = l0 * corr0 + s0;
        l1 = l1 * corr1 + s1;

#pragma unroll
        for (int j = 0; j < 8; j++) {
            co[j][0] *= corr0; co[j][1] *= corr0;
            co[j][2] *= corr1; co[j][3] *= corr1;
        }

        const int base = lane & ~3;
        const int s1l = base + (tg >> 1);
        const int s2l = s1l + 2;
        const bool odd = tg & 1;
#pragma unroll
        for (int kk = 0; kk < 8; kk++) {
            float v00 = __shfl_sync(0xffffffffu, cs[kk][0], s1l);
            float v01 = __shfl_sync(0xffffffffu, cs[kk][1], s1l);
            float v02 = __shfl_sync(0xffffffffu, cs[kk][0], s2l);
            float v03 = __shfl_sync(0xffffffffu, cs[kk][1], s2l);
            float v10 = __shfl_sync(0xffffffffu, cs[kk][2], s1l);
            float v11 = __shfl_sync(0xffffffffu, cs[kk][3], s1l);
            float v12 = __shfl_sync(0xffffffffu, cs[kk][2], s2l);
            float v13 = __shfl_sync(0xffffffffu, cs[kk][3], s2l);
            uint32_t ap[4];
            ap[0] = __float_as_uint(to_tf32(odd ? v01 : v00));
            ap[1] = __float_as_uint(to_tf32(odd ? v11 : v10));
            ap[2] = __float_as_uint(to_tf32(odd ? v03 : v02));
            ap[3] = __float_as_uint(to_tf32(odd ? v13 : v12));
#pragma unroll
            for (int j = 0; j < 8; j++) {
                uint32_t b0 = __float_as_uint(Vs[kk * 8 + tg][j * 8 + grp]);
                uint32_t b1 = __float_as_uint(Vs[kk * 8 + tg + 4][j * 8 + grp]);
                mma_tf32(co[j], ap, b0, b1);
            }
        }
        __syncthreads();
    }

    const float i0 = 1.f / l0;
    const float i1 = 1.f / l1;
    const int r0 = q0 + m0 + grp;
    float* op0 = d_attn + (size_t)(b * Sn + r0) * Dn + h * DH;
    float* op1 = d_attn + (size_t)(b * Sn + r0 + 8) * Dn + h * DH;
#pragma unroll
    for (int j = 0; j < 8; j++) {
        const int cc = j * 8 + 2 * tg;
        *(float2*)(op0 + cc) = make_float2(to_tf32(co[j][0] * i0), to_tf32(co[j][1] * i0));
        *(float2*)(op1 + cc) = make_float2(to_tf32(co[j][2] * i1), to_tf32(co[j][3] * i1));
    }
}

// ---------------------------------------------------------------------------
// Host launch
// ---------------------------------------------------------------------------
extern "C" void kernel_launch(void* const* d_in, const int* in_sizes, int n_in,
                              void* d_out, int out_size)
{
    const float* x    = (const float*)d_in[0];
    const float* qk_f = (const float*)d_in[1];
    const float* qk_r = (const float*)d_in[2];
    const float* v_f  = (const float*)d_in[3];
    const float* v_r  = (const float*)d_in[4];
    const float* Wgq  = (const float*)d_in[5];
    const float* Wgk  = (const float*)d_in[6];
    const float* Wgv  = (const float*)d_in[7];
    const float* W_O  = (const float*)d_in[8];
    float* out = (float*)d_out;

    float *x32, *bfeat, *cf, *attn, *wo32;
    cudaGetSymbolAddress((void**)&x32,   d_x32);
    cudaGetSymbolAddress((void**)&bfeat, d_Bfeat);
    cudaGetSymbolAddress((void**)&cf,    d_CF);
    cudaGetSymbolAddress((void**)&attn,  d_attn);
    cudaGetSymbolAddress((void**)&wo32,  d_Wo32);

    static bool attrDone = false;
    if (!attrDone) {
        cudaFuncSetAttribute(gemm_ca, cudaFuncAttributeMaxDynamicSharedMemorySize, SMEM_BYTES);
        cudaFuncSetAttribute(gemm_restore_ca, cudaFuncAttributeMaxDynamicSharedMemorySize, SMEM_BYTES);
        attrDone = true;
    }

    dim3 t256(256);

    // 0) tf32-round all GEMM operands
    pack_misc<<<(X_ELEMS + 3 * R_ELEMS) / 1024, t256>>>(x, qk_r, v_r, W_O);
    pack_bfeat<<<Dn, t256>>>(Wgq, Wgk, Wgv, qk_f, v_f);

    // 1) Merged logits + features: [2048, 2816] = x32 @ Bfeat
    gemm_ca<<<dim3(NF / 128, BS / 128, 1), t256, SMEM_BYTES>>>(
        x32, bfeat, cf, Dn, NF, NF, 0);

    // 2) Softmax + group -> gates
    gate_kernel<<<dim3(BS, 3), t256>>>();

    // 3) Weighted mix -> hQ, hK, hV
    mix_kernel<<<BS, 128>>>();

    // 4) Aeff for Q,K,V (tf32)
    aeff3_kernel<<<BS, t256>>>();

    // 5) Restore: Q,K,V in one launch (z = 0..2), outputs tf32
    gemm_restore_ca<<<dim3(Dn / 128, BS / 128, 3), t256, SMEM_BYTES>>>();

    // 6) Tensor-core causal attention
    flash_mma_kernel<<<dim3(Sn / 64, Bn * NH), 128>>>();

    // 7) Output projection -> d_out
    gemm_ca<<<dim3(Dn / 128, BS / 128, 1), t256, SMEM_BYTES>>>(
        attn, wo32, out, Dn, Dn, Dn, 0);
}